// round 9
// baseline (speedup 1.0000x reference)
#include <cuda_runtime.h>
#include <cuda_pipeline.h>

// N=4, Cin=4, Cout=4, K=5, H=W=128.
// d_in[0] = log_belief f32 [N,Cin,H,W], d_in[1] = log_kernel f32 [N,Cin,Cout*25,H,W]
// out = f32 [N,Cout,H,W]
//
// out[n,cout,oy,ox] = log sum_{cin,ky,kx in-bounds} exp(
//    bel[n,cin,oy+2-ky,ox+2-kx] + ker[n,cin,cout*25+ky*5+kx, oy+2-ky, ox+2-kx])
//
// Warp-private streaming: warp w owns cin=w (25 kernel rows), cp.asyncs them
// through its own smem ring (depth 8) and consumes them itself -> no block
// barriers in the main loop, only __syncwarp. Each lane covers 4 output
// columns. Branch-free bounds: belief staged as (b+SHIFT)*log2e with -1e30
// halo; ring rows have zeroed 4-elem halos both sides so kv reads at
// x+6-kx ([2,133]) never clamp; invalid taps -> exp2(-huge) == 0.

#define NN      4
#define CIN     4
#define COUT    4
#define KSZ     5
#define HH      128
#define WW      128
#define KK      25
#define PLANE   (HH*WW)
#define SHIFT   12.0f
#define NEGBIG  1e30f
#define L2E     1.4426950408889634f
#define LN2     0.6931471805599453f
#define WEXT    132
#define RSTRIDE 136              // 4 halo + 128 payload + 4 halo
#define NG      20
#define DPTH    8
#define NSLOT   (DPTH+1)

__global__ __launch_bounds__(128, 6)
void prop_belief_kernel(const float* __restrict__ bel,
                        const float* __restrict__ ker,
                        float* __restrict__ out) {
    const int oy   = blockIdx.x;
    const int cout = blockIdx.y;
    const int n    = blockIdx.z;
    const int w    = threadIdx.x >> 5;   // warp id == cin
    const int lane = threadIdx.x & 31;

    __shared__ __align__(16) float ring[CIN][NSLOT][RSTRIDE];
    __shared__ float sb[NG][WEXT];       // haloed belief, (b+SHIFT)*log2e
    __shared__ float psum[CIN][WW];      // per-warp partial sums

    // Zero both ring halos once (cp.async only ever writes [4..131]).
    for (int i = threadIdx.x; i < CIN * NSLOT * 8; i += 128) {
        const int row = i >> 3;                    // 0..35
        const int h   = i & 7;
        const int idx = (h < 4) ? h : (128 + h);   // 0..3 or 132..135
        ring[row / NSLOT][row % NSLOT][idx] = 0.f;
    }

    // Plane index for (n, cin=w, cout, pk): n*400 + w*100 + cout*25 + pk.
    const float* kbase = ker + ((size_t)(n * (CIN * COUT * KK)
                                + w * (COUT * KK) + cout * KK)) * PLANE;

    // Issue this warp's row for stage t (tap pk = t).
    auto issue_row = [&](int t) {
        const int ky = t / 5;
        int ys = oy + 2 - ky;
        ys = ys < 0 ? 0 : (ys > HH - 1 ? HH - 1 : ys);
        const float* src = kbase + (size_t)t * PLANE + (size_t)ys * WW + lane * 4;
        __pipeline_memcpy_async(&ring[w][t % NSLOT][4 + lane * 4], src, 16);
    };

    #pragma unroll
    for (int t = 0; t < DPTH; ++t) {
        issue_row(t);
        __pipeline_commit();
    }

    // Stage belief rows (all cin, shared): sb[g][xs+2].
    #pragma unroll 1
    for (int i = threadIdx.x; i < NG * WEXT; i += 128) {
        const int g  = i / WEXT;
        const int xi = i - g * WEXT;
        const int cin = g / KSZ, ky = g % KSZ;
        const int ys = oy + 2 - ky;
        const int xs = xi - 2;
        float v = -NEGBIG;
        if (ys >= 0 && ys < HH && xs >= 0 && xs < WW)
            v = (__ldg(bel + ((size_t)(n * CIN + cin) * HH + ys) * WW + xs) + SHIFT) * L2E;
        sb[g][xi] = v;
    }
    __syncthreads();   // publishes sb + ring halos to all warps

    float a0 = 0.f, a1 = 0.f, a2 = 0.f, a3 = 0.f;

    // Main loop: 25 stages, warp-private, no block barriers.
    #pragma unroll
    for (int t = 0; t < KK; ++t) {
        __pipeline_wait_prior(DPTH - 1);
        __syncwarp();    // all lanes' copies for stage t visible warp-wide

        const int ky = t / 5;            // compile-time constants
        const int kx = t - ky * 5;
        const float* krow = &ring[w][t % NSLOT][0];
        const float* brow = &sb[w * KSZ + ky][0];

        #pragma unroll
        for (int c = 0; c < 4; ++c) {
            const int xcol = lane + 32 * c;
            const float kv  = krow[xcol + 6 - kx];
            const float bvl = brow[xcol + 4 - kx];     // -1e30 if invalid
            const float e   = exp2f(fmaf(kv, L2E, bvl));
            if      (c == 0) a0 += e;
            else if (c == 1) a1 += e;
            else if (c == 2) a2 += e;
            else             a3 += e;
        }

        if (t + DPTH < KK) issue_row(t + DPTH);
        __pipeline_commit();   // uniform group count
    }

    // Cross-warp (= cross-cin) combine.
    psum[w][lane]      = a0;
    psum[w][lane + 32] = a1;
    psum[w][lane + 64] = a2;
    psum[w][lane + 96] = a3;
    __syncthreads();

    const int x = threadIdx.x;
    const float s = (psum[0][x] + psum[1][x]) + (psum[2][x] + psum[3][x]);
    out[((size_t)(n * COUT + cout) * HH + oy) * WW + x] =
        __log2f(s) * LN2 - SHIFT;
}

extern "C" void kernel_launch(void* const* d_in, const int* in_sizes, int n_in,
                              void* d_out, int out_size) {
    const float* bel = (const float*)d_in[0];
    const float* ker = (const float*)d_in[1];
    float* out = (float*)d_out;

    dim3 grid(HH, COUT, NN);   // (oy, cout, n)
    dim3 block(128);
    prop_belief_kernel<<<grid, block>>>(bel, ker, out);
}